// round 2
// baseline (speedup 1.0000x reference)
#include <cuda_runtime.h>

// rho' = (A (x) B (x) C) rho (A (x) B (x) C)^T, A,B = 16x16 rotations active
// only on the top-left 4x4 block, C = 4x4. flat = r*64 + c*4 + j.
//
// One kernel applies L = A(x)B(x)C to every ROW of its input and writes the
// result TRANSPOSED. Launched twice. Rows split into 4 independent 256-col
// chunks: the r-mode (stride 64) only couples r<4, i.e. columns 0..255, so
// chunks 1..3 skip it. Grid = 128 row-batches x 4 chunks = 512 blocks.

#define RPB 8             // rows per block
#define RS  272           // smem row stride: 256 + 4 pad per 64-block
// f(col) = col + 4*(col>>6)  (pad every 64 columns; keeps float4 alignment)

__device__ __align__(16) float g_scratch[1024 * 1024];

__global__ __launch_bounds__(256, 8)
void rbs_xform(const float* __restrict__ in,
               float* __restrict__ out,
               const float* __restrict__ thetas)
{
    __shared__ float s[RPB * RS];
    __shared__ float sM[3][16];   // 0: A4 (row), 1: B4 (col), 2: C4 (ch)

    const int t     = threadIdx.x;
    const int chunk = blockIdx.x;          // 0..3 (256 columns each)
    const int row0  = blockIdx.y * RPB;    // 8 rows
    const int cbase = chunk * 256;

    // ---- issue global loads early ----
    const float4* in4 = reinterpret_cast<const float4*>(in);
    float4 x0, x1;
    {
        int s0 = t, s1 = t + 256;                       // slots: 8 rows x 64 f4
        int rr0 = s0 >> 6, tl0 = s0 & 63;
        int rr1 = s1 >> 6, tl1 = s1 & 63;
        x0 = in4[(size_t)(row0 + rr0) * 256 + chunk * 64 + tl0];
        x1 = in4[(size_t)(row0 + rr1) * 256 + chunk * 64 + tl1];
    }

    // ---- build the three 4x4 Givens products from thetas ----
    if (t < 3) {
        float M[16] = {1,0,0,0, 0,1,0,0, 0,0,1,0, 0,0,0,1};
        const int pi[6] = {0,0,0,1,1,2};
        const int pj[6] = {1,2,3,2,3,3};
#pragma unroll
        for (int g = 0; g < 6; ++g) {
            float th = thetas[t * 6 + g];
            float c = cosf(th), sn = sinf(th);
            int i = pi[g], j = pj[g];
#pragma unroll
            for (int k = 0; k < 4; ++k) {
                float ai = M[i*4 + k], aj = M[j*4 + k];
                M[i*4 + k] =  c * ai + sn * aj;    // M <- G(i,j,th) * M
                M[j*4 + k] = -sn * ai +  c * aj;
            }
        }
#pragma unroll
        for (int k = 0; k < 16; ++k) sM[t][k] = M[k];
    }
    __syncthreads();

    // ---- stage 1: j-mode (C4) fused with store to padded shared tile ----
    {
        float c00=sM[2][0],  c01=sM[2][1],  c02=sM[2][2],  c03=sM[2][3];
        float c10=sM[2][4],  c11=sM[2][5],  c12=sM[2][6],  c13=sM[2][7];
        float c20=sM[2][8],  c21=sM[2][9],  c22=sM[2][10], c23=sM[2][11];
        float c30=sM[2][12], c31=sM[2][13], c32=sM[2][14], c33=sM[2][15];
#pragma unroll
        for (int h = 0; h < 2; ++h) {
            int slot = t + 256 * h;
            int rr = slot >> 6, tl = slot & 63;
            float4 v = (h == 0) ? x0 : x1;
            float4 y;
            y.x = c00*v.x + c01*v.y + c02*v.z + c03*v.w;
            y.y = c10*v.x + c11*v.y + c12*v.z + c13*v.w;
            y.z = c20*v.x + c21*v.y + c22*v.z + c23*v.w;
            y.w = c30*v.x + c31*v.y + c32*v.z + c33*v.w;
            int f = 4 * tl + 4 * (tl >> 4);            // pad every 64 cols
            *reinterpret_cast<float4*>(&s[rr * RS + f]) = y;
        }
    }
    __syncthreads();

    // ---- stage 2: c-mode (B4, c in 0..3, stride 4 within each 64-block) ----
    // groups: (rr, k, j) = 8*4*4 = 128; element offset f = 68k + 4c + j
    if (t < 128) {
        float b00=sM[1][0],  b01=sM[1][1],  b02=sM[1][2],  b03=sM[1][3];
        float b10=sM[1][4],  b11=sM[1][5],  b12=sM[1][6],  b13=sM[1][7];
        float b20=sM[1][8],  b21=sM[1][9],  b22=sM[1][10], b23=sM[1][11];
        float b30=sM[1][12], b31=sM[1][13], b32=sM[1][14], b33=sM[1][15];
        int rr = t >> 4, k = (t >> 2) & 3, j = t & 3;
        float* base = &s[rr * RS + 68 * k + j];
        float v0 = base[0], v1 = base[4], v2 = base[8], v3 = base[12];
        base[0]  = b00*v0 + b01*v1 + b02*v2 + b03*v3;
        base[4]  = b10*v0 + b11*v1 + b12*v2 + b13*v3;
        base[8]  = b20*v0 + b21*v1 + b22*v2 + b23*v3;
        base[12] = b30*v0 + b31*v1 + b32*v2 + b33*v3;
    }
    __syncthreads();

    // ---- stage 3: r-mode (A4, r in 0..3, stride 64) — chunk 0 only ----
    if (chunk == 0) {
        float a00=sM[0][0],  a01=sM[0][1],  a02=sM[0][2],  a03=sM[0][3];
        float a10=sM[0][4],  a11=sM[0][5],  a12=sM[0][6],  a13=sM[0][7];
        float a20=sM[0][8],  a21=sM[0][9],  a22=sM[0][10], a23=sM[0][11];
        float a30=sM[0][12], a31=sM[0][13], a32=sM[0][14], a33=sM[0][15];
        // groups: (rr, c, j) = 8*16*4 = 512; offset f = 68r + 4c + j
#pragma unroll
        for (int h = 0; h < 2; ++h) {
            int it = t + 256 * h;
            int j  = it & 3;
            int c  = (it >> 2) & 15;
            int rr = it >> 6;
            float* base = &s[rr * RS + 4 * c + j];
            float v0 = base[0], v1 = base[68], v2 = base[136], v3 = base[204];
            base[0]   = a00*v0 + a01*v1 + a02*v2 + a03*v3;
            base[68]  = a10*v0 + a11*v1 + a12*v2 + a13*v3;
            base[136] = a20*v0 + a21*v1 + a22*v2 + a23*v3;
            base[204] = a30*v0 + a31*v1 + a32*v2 + a33*v3;
        }
    }
    __syncthreads();

    // ---- stage 4: transposed write-out, 32B per thread (full sectors) ----
    {
        int f = t + 4 * (t >> 6);                      // padded column offset
        float4 a, b;
        a.x = s[0 * RS + f]; a.y = s[1 * RS + f];
        a.z = s[2 * RS + f]; a.w = s[3 * RS + f];
        b.x = s[4 * RS + f]; b.y = s[5 * RS + f];
        b.z = s[6 * RS + f]; b.w = s[7 * RS + f];
        float4* o = reinterpret_cast<float4*>(out + (size_t)(cbase + t) * 1024 + row0);
        o[0] = a;
        o[1] = b;
    }
}

extern "C" void kernel_launch(void* const* d_in, const int* in_sizes, int n_in,
                              void* d_out, int out_size)
{
    const float* state  = nullptr;
    const float* thetas = nullptr;
    for (int i = 0; i < n_in; ++i) {
        if (in_sizes[i] == 18 && !thetas)
            thetas = (const float*)d_in[i];
        else if (in_sizes[i] == 1024 * 1024 && !state)
            state = (const float*)d_in[i];
    }

    float* scratch = nullptr;
    cudaGetSymbolAddress((void**)&scratch, g_scratch);

    float* out = (float*)d_out;
    dim3 grid(4, 128);
    rbs_xform<<<grid, 256>>>(state, scratch, thetas);   // Z^T  (Z = rho L^T)
    rbs_xform<<<grid, 256>>>(scratch, out, thetas);     // L rho L^T
}

// round 5
// speedup vs baseline: 1.5483x; 1.5483x over previous
#include <cuda_runtime.h>

// rho' = L rho L^T,  L = A (x) B (x) C  (flat index = r*64 + c*4 + j,
// r,c in [0,16), j in [0,4)).  A,B are identity outside indices 0..3, so the
// index space splits into independent coupling classes:
//   D : {r<4, c<4}                -> one class of 64 indices
//   Cc: {r<4, c fixed >=4}        -> 12 classes of 16
//   Bc: {r fixed >=4, c<4}        -> 12 classes of 16
//   Am: {r>=4, c>=4}              -> 144 classes of 4 (merged 4-at-a-time)
// out[I,J] = (L|I) rho[I,J] (L|J)^T per class pair, so ONE kernel: each block
// owns a row-class x column range of whole column classes, applies row mixing
// (in registers) and column mixing (in padded smem), reads/writes each element
// exactly once, fully coalesced. No scratch, no second pass, no transpose.

#define RS16 272   // 16-row tiles: 256 cols + 4 pad per 64-col block
#define RSD   80   // 64-row tiles:  64 cols + 4 pad per 16-col block

__device__ __forceinline__ void mix4s(float* p, const int st, const float* M)
{
    float v0 = p[0], v1 = p[st], v2 = p[2*st], v3 = p[3*st];
    p[0]    = M[0] *v0 + M[1] *v1 + M[2] *v2 + M[3] *v3;
    p[st]   = M[4] *v0 + M[5] *v1 + M[6] *v2 + M[7] *v3;
    p[2*st] = M[8] *v0 + M[9] *v1 + M[10]*v2 + M[11]*v3;
    p[3*st] = M[12]*v0 + M[13]*v1 + M[14]*v2 + M[15]*v3;
}

__device__ __forceinline__ void mix4r(float* v, const int st, const float* M)
{
    float v0 = v[0], v1 = v[st], v2 = v[2*st], v3 = v[3*st];
    v[0]    = M[0] *v0 + M[1] *v1 + M[2] *v2 + M[3] *v3;
    v[st]   = M[4] *v0 + M[5] *v1 + M[6] *v2 + M[7] *v3;
    v[2*st] = M[8] *v0 + M[9] *v1 + M[10]*v2 + M[11]*v3;
    v[3*st] = M[12]*v0 + M[13]*v1 + M[14]*v2 + M[15]*v3;
}

__global__ __launch_bounds__(256)
void rbs_fused(const float* __restrict__ in, float* __restrict__ out,
               const float* __restrict__ thetas)
{
    __shared__ float s[64 * RSD];   // 20480 B; 16*RS16 = 4352 floats also fits
    __shared__ float sM[3][16];     // 0:A (row gates), 1:B (col), 2:C (ch)

    const int t = threadIdx.x;
    const int b = blockIdx.x;

    // ---- build the three 4x4 Givens products ----
    if (t < 3) {
        float M[16] = {1,0,0,0, 0,1,0,0, 0,0,1,0, 0,0,0,1};
        const int pi[6] = {0,0,0,1,1,2};
        const int pj[6] = {1,2,3,2,3,3};
#pragma unroll
        for (int g = 0; g < 6; ++g) {
            float th = thetas[t * 6 + g];
            float cc = cosf(th), sn = sinf(th);
            int i = pi[g], j = pj[g];
#pragma unroll
            for (int k = 0; k < 4; ++k) {
                float ai = M[i*4 + k], aj = M[j*4 + k];
                M[i*4 + k] =  cc * ai + sn * aj;   // M <- G * M
                M[j*4 + k] = -sn * ai + cc * aj;
            }
        }
#pragma unroll
        for (int k = 0; k < 16; ++k) sM[t][k] = M[k];
    }

    const float4* in4  = reinterpret_cast<const float4*>(in);
    float4*       out4 = reinterpret_cast<float4*>(out);

    if (b < 16) {
        // ================= type D: 64 rows {r<4,c<4} x 64 cols =============
        const int ccq = b & 3, chunk = b >> 2;   // c-quarter, rc-chunk
        // local row l = rr*16 + cc*4 + j ; global col (chunk*4+rcl)*64 + (ccq*4+w)*4 + jc
#pragma unroll
        for (int h = 0; h < 4; ++h) {
            int idx = t + 256*h;
            int l = idx >> 4, c4 = idx & 15;
            int rcl = c4 >> 2, w = c4 & 3;
            int grow = (l >> 4) * 64 + (l & 15);
            int gc4  = (chunk*4 + rcl)*16 + ccq*4 + w;
            float4 v = in4[grow*256 + gc4];
            *reinterpret_cast<float4*>(&s[l*RSD + rcl*20 + w*4]) = v;
        }
        __syncthreads();
        // row C (j) + row B (cc) fused in registers: thread owns (rr, col)
        {
            float C4[16], B4[16];
#pragma unroll
            for (int k = 0; k < 16; ++k) { C4[k] = sM[2][k]; B4[k] = sM[1][k]; }
            int rr = t >> 6, q = t & 63;
            int pc = q + 4*(q >> 4);
            float v[16];
#pragma unroll
            for (int k = 0; k < 16; ++k) v[k] = s[(rr*16 + k)*RSD + pc];
#pragma unroll
            for (int cc = 0; cc < 4; ++cc) mix4r(&v[cc*4], 1, C4);
#pragma unroll
            for (int j = 0; j < 4; ++j)    mix4r(&v[j], 4, B4);
#pragma unroll
            for (int k = 0; k < 16; ++k) s[(rr*16 + k)*RSD + pc] = v[k];
        }
        __syncthreads();
        // row A across rr (stride 16 rows)
        {
            float A4[16];
#pragma unroll
            for (int k = 0; k < 16; ++k) A4[k] = sM[0][k];
#pragma unroll
            for (int h = 0; h < 4; ++h) {
                int g = t + 256*h;
                int ccj = g >> 6, q = g & 63;
                int pc = q + 4*(q >> 4);
                mix4s(&s[ccj*RSD + pc], 16*RSD, A4);
            }
        }
        __syncthreads();
        // col C (jc, stride 1): 64 rows x 4 rcl x 4 ccl = 1024 groups
        {
            float C4[16];
#pragma unroll
            for (int k = 0; k < 16; ++k) C4[k] = sM[2][k];
#pragma unroll
            for (int h = 0; h < 4; ++h) {
                int g = t + 256*h;
                int l = g >> 4, rcl = (g >> 2) & 3, ccl = g & 3;
                mix4s(&s[l*RSD + rcl*20 + ccl*4], 1, C4);
            }
        }
        __syncthreads();
        // col B (c<4): only the ccq==0 quarter holds those columns
        if (ccq == 0) {
            float B4[16];
#pragma unroll
            for (int k = 0; k < 16; ++k) B4[k] = sM[1][k];
#pragma unroll
            for (int h = 0; h < 4; ++h) {
                int g = t + 256*h;
                int l = g >> 4, rcl = (g >> 2) & 3, j = g & 3;
                mix4s(&s[l*RSD + rcl*20 + j], 4, B4);
            }
            __syncthreads();
        }
        // col A (rc<4): only chunk 0
        if (chunk == 0) {
            float A4[16];
#pragma unroll
            for (int k = 0; k < 16; ++k) A4[k] = sM[0][k];
#pragma unroll
            for (int h = 0; h < 4; ++h) {
                int g = t + 256*h;
                int l = g >> 4, ccl = (g >> 2) & 3, j = g & 3;
                mix4s(&s[l*RSD + ccl*4 + j], 20, A4);
            }
            __syncthreads();
        }
        // store (mirror of load)
#pragma unroll
        for (int h = 0; h < 4; ++h) {
            int idx = t + 256*h;
            int l = idx >> 4, c4 = idx & 15;
            int rcl = c4 >> 2, w = c4 & 3;
            int grow = (l >> 4) * 64 + (l & 15);
            int gc4  = (chunk*4 + rcl)*16 + ccq*4 + w;
            out4[grow*256 + gc4] =
                *reinterpret_cast<float4*>(&s[l*RSD + rcl*20 + w*4]);
        }
    } else {
        // ============ 16-row classes x 256-col chunk =======================
        int typ, chunk, rb_r = 0, rb_c = 0, rb_c0 = 0;
        if (b < 64)       { typ = 0; int id = b - 16;  chunk = id & 3; rb_r = 4 + (id >> 2); }            // Bc: rows r*64 + l
        else if (b < 112) { typ = 1; int id = b - 64;  chunk = id & 3; rb_c = 4 + (id >> 2); }            // Cc: rows (l>>2)*64 + c*4 + (l&3)
        else              { typ = 2; int id = b - 112; chunk = id & 3; int g = id >> 2;
                            rb_r = 4 + g / 3; rb_c0 = 4 + (g % 3) * 4; }                                  // Am: rows r*64 + c0*4 + l
        // load 16 x 256
#pragma unroll
        for (int h = 0; h < 4; ++h) {
            int idx = t + 256*h;
            int l = idx >> 6, c4 = idx & 63;
            int grow = (typ == 0) ? rb_r*64 + l
                     : (typ == 1) ? (l >> 2)*64 + rb_c*4 + (l & 3)
                                  : rb_r*64 + rb_c0*4 + l;
            float4 v = in4[grow*256 + chunk*64 + c4];
            *reinterpret_cast<float4*>(&s[l*RS16 + (c4 >> 4)*68 + (c4 & 15)*4]) = v;
        }
        __syncthreads();
        // row mixing fully in registers: thread owns one column (16 values)
        {
            float C4[16], M2[16];
            const float* msrc = (typ == 0) ? sM[1] : sM[0];
#pragma unroll
            for (int k = 0; k < 16; ++k) { C4[k] = sM[2][k]; M2[k] = msrc[k]; }
            int pc = t + 4*(t >> 6);
            float v[16];
#pragma unroll
            for (int k = 0; k < 16; ++k) v[k] = s[k*RS16 + pc];
#pragma unroll
            for (int qd = 0; qd < 4; ++qd) mix4r(&v[qd*4], 1, C4);   // C on j
            if (typ != 2) {
#pragma unroll
                for (int j = 0; j < 4; ++j) mix4r(&v[j], 4, M2);     // B or A
            }
#pragma unroll
            for (int k = 0; k < 16; ++k) s[k*RS16 + pc] = v[k];
        }
        __syncthreads();
        // col C (jc): ALL 16 rows x 4 bl x 16 c = 1024 groups
        {
            float C4[16];
#pragma unroll
            for (int k = 0; k < 16; ++k) C4[k] = sM[2][k];
#pragma unroll
            for (int h = 0; h < 4; ++h) {
                int g = t + 256*h;
                int l = g >> 6, bl = (g >> 4) & 3, c = g & 15;
                mix4s(&s[l*RS16 + bl*68 + c*4], 1, C4);
            }
        }
        __syncthreads();
        // col B (c<4 within each 64-block): 16 x 4 x 4 = 256 groups
        {
            float B4[16];
#pragma unroll
            for (int k = 0; k < 16; ++k) B4[k] = sM[1][k];
            int l = t >> 4, bl = (t >> 2) & 3, j = t & 3;
            mix4s(&s[l*RS16 + bl*68 + j], 4, B4);
        }
        __syncthreads();
        // col A (rc<4): only chunk 0
        if (chunk == 0) {
            float A4[16];
#pragma unroll
            for (int k = 0; k < 16; ++k) A4[k] = sM[0][k];
#pragma unroll
            for (int h = 0; h < 4; ++h) {
                int g = t + 256*h;
                int l = g >> 6, cc = (g >> 2) & 15, j = g & 3;
                mix4s(&s[l*RS16 + cc*4 + j], 68, A4);
            }
            __syncthreads();
        }
        // store (mirror of load)
#pragma unroll
        for (int h = 0; h < 4; ++h) {
            int idx = t + 256*h;
            int l = idx >> 6, c4 = idx & 63;
            int grow = (typ == 0) ? rb_r*64 + l
                     : (typ == 1) ? (l >> 2)*64 + rb_c*4 + (l & 3)
                                  : rb_r*64 + rb_c0*4 + l;
            out4[grow*256 + chunk*64 + c4] =
                *reinterpret_cast<float4*>(&s[l*RS16 + (c4 >> 4)*68 + (c4 & 15)*4]);
        }
    }
}

extern "C" void kernel_launch(void* const* d_in, const int* in_sizes, int n_in,
                              void* d_out, int out_size)
{
    const float* state  = nullptr;
    const float* thetas = nullptr;
    for (int i = 0; i < n_in; ++i) {
        if (in_sizes[i] == 18 && !thetas)
            thetas = (const float*)d_in[i];
        else if (in_sizes[i] == 1024 * 1024 && !state)
            state = (const float*)d_in[i];
    }
    rbs_fused<<<256, 256>>>(state, (float*)d_out, thetas);
}